// round 12
// baseline (speedup 1.0000x reference)
#include <cuda_runtime.h>
#include <cuda_bf16.h>

// Problem constants
#define N 4096
#define D 512
#define NC 100          // real classes
#define NCP 128         // padded classes
#define ROWS_B 32       // rows per GEMM block
#define KT 32           // k-tile
#define NT (D / KT)     // 16 tiles
#define NBLK (N / ROWS_B)   // 128 gemm blocks (single wave: 128 < 148 SMs)

// smem carve (floats)
#define BS_STRIDE 516                       // 516 mod 32 = 4 -> conflict-free mma reads
#define BS_FLOATS (NC * BS_STRIDE)          // 51600
#define AS_FLOATS (2 * ROWS_B * 36)         // 2304 (double-buffered A tile)
#define SMEM_FLOATS (BS_FLOATS + AS_FLOATS + NCP + 128)
#define SMEM_BYTES (SMEM_FLOATS * 4 + 24 * 8)

// Scratch (device globals; load-time zeroed; gemm tail restores all to 0)
__device__ __align__(16) float g_txt_n[N * D];   // normalized text features
__device__ float g_d[N];                          // per-row <img_n, txt_n>
__device__ __align__(16) float g_G[NC * D];       // class sums of img_n, [c][d]
__device__ int    g_cnt[NCP];                     // class counts
__device__ double g_neg;                          // neg accumulator
__device__ double g_sumd;                         // sum_i d_i
__device__ double g_sumexpd;                      // sum_i exp(d_i)
__device__ unsigned int g_fin;                    // epilogue ticket
__device__ unsigned int g_reads;                  // "done reading G/cnt" counter
__device__ unsigned int g_cleanfin;               // cleaner ticket

__device__ __forceinline__ unsigned tf32(float x) {
    unsigned r;
    asm("cvt.rna.tf32.f32 %0, %1;" : "=r"(r) : "f"(x));
    return r;
}

// ---------------------------------------------------------------------------
// Kernel 1 (R8-proven, unchanged): normalize, store txt_n + d_i, v4-REDG -> G.
// grid = N blocks, 128 threads (thread owns 4 consecutive dims, float4).
// ---------------------------------------------------------------------------
__global__ void __launch_bounds__(128) rownorm_kernel(
    const float* __restrict__ img,
    const float* __restrict__ txt,
    const int* __restrict__ labels)
{
    const int i    = blockIdx.x;
    const int tid  = threadIdx.x;
    const int lane = tid & 31;
    const int warp = tid >> 5;

    const float4 a = reinterpret_cast<const float4*>(img + (size_t)i * D)[tid];
    const float4 b = reinterpret_cast<const float4*>(txt + (size_t)i * D)[tid];

    float sii = a.x*a.x + a.y*a.y + a.z*a.z + a.w*a.w;
    float stt = b.x*b.x + b.y*b.y + b.z*b.z + b.w*b.w;
    float sit = a.x*b.x + a.y*b.y + a.z*b.z + a.w*b.w;

    #pragma unroll
    for (int off = 16; off > 0; off >>= 1) {
        sii += __shfl_xor_sync(0xffffffffu, sii, off);
        stt += __shfl_xor_sync(0xffffffffu, stt, off);
        sit += __shfl_xor_sync(0xffffffffu, sit, off);
    }
    __shared__ float red[3][4];
    if (lane == 0) { red[0][warp] = sii; red[1][warp] = stt; red[2][warp] = sit; }
    __syncthreads();
    sii = red[0][0] + red[0][1] + red[0][2] + red[0][3];
    stt = red[1][0] + red[1][1] + red[1][2] + red[1][3];
    sit = red[2][0] + red[2][1] + red[2][2] + red[2][3];

    const float rimg = rsqrtf(sii);
    const float rtxt = rsqrtf(stt);
    int c = labels[i];
    c = min(max(c, 0), NC - 1);

    float4 tn;
    tn.x = b.x * rtxt; tn.y = b.y * rtxt; tn.z = b.z * rtxt; tn.w = b.w * rtxt;
    reinterpret_cast<float4*>(g_txt_n + (size_t)i * D)[tid] = tn;

    float* gc = g_G + (size_t)c * D + tid * 4;
    asm volatile("red.global.add.v4.f32 [%0], {%1, %2, %3, %4};"
                 :: "l"(gc), "f"(a.x * rimg), "f"(a.y * rimg),
                    "f"(a.z * rimg), "f"(a.w * rimg)
                 : "memory");

    if (tid == 0) {
        g_d[i] = sit * rimg * rtxt;
        atomicAdd(&g_cnt[c], 1);
    }
}

// ---------------------------------------------------------------------------
// Kernel 2: tf32 mma GEMM with B fully smem-resident + neg + loss + self-clean.
// grid = 128 blocks, 256 threads (8 warps).
// Warp (m = w&1, nq = w>>1) owns rows 16m..16m+15 x classes 32nq..32nq+31.
// FIX vs R11: B fragment reads use GLOBAL k (t*KT + kk0 + tig) since B is
// fully resident, not tile-staged.
// ---------------------------------------------------------------------------
__global__ void __launch_bounds__(256) gemm_neg_kernel(float* __restrict__ out)
{
    extern __shared__ float smem[];
    float*  Bs    = smem;                       // [NC][BS_STRIDE] tf32 bits
    float*  Asb   = smem + BS_FLOATS;           // [2][32][36] tf32 bits
    float*  nsm   = Asb + AS_FLOATS;            // [NCP]
    float*  Ssm   = nsm + NCP;                  // [32][4]
    double* bred  = (double*)(Ssm + 128);       // [8][3]

    const int tid  = threadIdx.x;
    const int lane = tid & 31;
    const int warp = tid >> 5;
    const int g    = lane >> 2;        // group id 0..7
    const int tig  = lane & 3;         // thread in group 0..3
    const int m    = warp & 1;         // row half
    const int nq   = warp >> 1;        // class quadrant 0..3
    const int row0 = blockIdx.x * ROWS_B;

    // ---- stage ALL of B (tf32) + counts; these are the only G/cnt reads ----
    if (tid < NCP) nsm[tid] = (float)g_cnt[tid];
    #pragma unroll 5
    for (int e = 0; e < 50; e++) {
        const int idx = e * 256 + tid;          // 12800 float4s of G
        const int c   = idx >> 7;               // class
        const int k4  = (idx & 127) * 4;
        const float4 v = *reinterpret_cast<const float4*>(&g_G[(size_t)c * D + k4]);
        float* dst = &Bs[c * BS_STRIDE + k4];
        dst[0] = __uint_as_float(tf32(v.x));
        dst[1] = __uint_as_float(tf32(v.y));
        dst[2] = __uint_as_float(tf32(v.z));
        dst[3] = __uint_as_float(tf32(v.w));
    }
    __syncthreads();   // staging stores drained => all G/cnt loads completed
    if (tid == 0) {
        __threadfence();
        atomicAdd(&g_reads, 1u);   // G/cnt fully consumed by this block
    }

    // ---- mainloop: stream A tiles through double-buffered smem ----
    float acc[4][4] = {};              // [n-tile][c0..c3]

    const int ar  = tid >> 3;          // A row 0..31
    const int ak4 = (tid & 7) * 4;     // k offset 0..28

    // B fragment predication (loop-invariant): class cb = 32nq + 8nt + g
    const float* brow[4];
    bool bval[4];
    #pragma unroll
    for (int nt = 0; nt < 4; nt++) {
        const int cb = 32 * nq + 8 * nt + g;
        bval[nt] = (cb < NC);
        brow[nt] = &Bs[(bval[nt] ? cb : 0) * BS_STRIDE];
    }

    // stage tile 0 into buffer 0
    {
        const float4 v = *reinterpret_cast<const float4*>(&g_txt_n[(size_t)(row0 + ar) * D + ak4]);
        float* dst = &Asb[0 * 1152 + ar * 36 + ak4];
        dst[0] = __uint_as_float(tf32(v.x));
        dst[1] = __uint_as_float(tf32(v.y));
        dst[2] = __uint_as_float(tf32(v.z));
        dst[3] = __uint_as_float(tf32(v.w));
    }

    for (int t = 0; t < NT; t++) {
        __syncthreads();               // buffer (t&1) staged; buffer (t-1)&1 free
        const float* As = &Asb[(t & 1) * 1152];
        const int kt = t * KT;         // GLOBAL k offset for resident B

        float4 v;
        if (t < NT - 1)
            v = *reinterpret_cast<const float4*>(&g_txt_n[(size_t)(row0 + ar) * D + kt + KT + ak4]);

        #pragma unroll
        for (int ks = 0; ks < 4; ks++) {
            const int kk0 = ks * 8;
            const unsigned a0 = __float_as_uint(As[(16*m + g    ) * 36 + kk0 + tig]);
            const unsigned a1 = __float_as_uint(As[(16*m + g + 8) * 36 + kk0 + tig]);
            const unsigned a2 = __float_as_uint(As[(16*m + g    ) * 36 + kk0 + tig + 4]);
            const unsigned a3 = __float_as_uint(As[(16*m + g + 8) * 36 + kk0 + tig + 4]);
            #pragma unroll
            for (int nt = 0; nt < 4; nt++) {
                const unsigned b0 = bval[nt] ? __float_as_uint(brow[nt][kt + kk0 + tig])     : 0u;
                const unsigned b1 = bval[nt] ? __float_as_uint(brow[nt][kt + kk0 + tig + 4]) : 0u;
                asm volatile(
                    "mma.sync.aligned.m16n8k8.row.col.f32.tf32.tf32.f32 "
                    "{%0,%1,%2,%3}, {%4,%5,%6,%7}, {%8,%9}, {%0,%1,%2,%3};"
                    : "+f"(acc[nt][0]), "+f"(acc[nt][1]),
                      "+f"(acc[nt][2]), "+f"(acc[nt][3])
                    : "r"(a0), "r"(a1), "r"(a2), "r"(a3), "r"(b0), "r"(b1));
            }
        }

        if (t < NT - 1) {
            float* dst = &Asb[((t + 1) & 1) * 1152 + ar * 36 + ak4];
            dst[0] = __uint_as_float(tf32(v.x));
            dst[1] = __uint_as_float(tf32(v.y));
            dst[2] = __uint_as_float(tf32(v.z));
            dst[3] = __uint_as_float(tf32(v.w));
        }
    }

    // ---- Epilogue (R10-validated layout) ----
    // Thread holds C at rows r0=16m+g, r1=r0+8; cols 32nq+8nt+2tig(+1).
    float s0 = 0.f, s1 = 0.f;
    #pragma unroll
    for (int nt = 0; nt < 4; nt++) {
        s0 += acc[nt][0] + acc[nt][1];
        s1 += acc[nt][2] + acc[nt][3];
    }
    s0 += __shfl_xor_sync(0xffffffffu, s0, 1);
    s0 += __shfl_xor_sync(0xffffffffu, s0, 2);
    s1 += __shfl_xor_sync(0xffffffffu, s1, 1);
    s1 += __shfl_xor_sync(0xffffffffu, s1, 2);
    const int r0 = 16*m + g, r1 = r0 + 8;
    if (tig == 0) { Ssm[r0 * 4 + nq] = s0; Ssm[r1 * 4 + nq] = s1; }
    __syncthreads();

    const float S0 = Ssm[r0*4+0] + Ssm[r0*4+1] + Ssm[r0*4+2] + Ssm[r0*4+3];
    const float S1 = Ssm[r1*4+0] + Ssm[r1*4+1] + Ssm[r1*4+2] + Ssm[r1*4+3];
    float p = 0.f;
    #pragma unroll
    for (int nt = 0; nt < 4; nt++) {
        const int cA = 32*nq + 8*nt + 2*tig;
        const float nA = nsm[cA], nB = nsm[cA + 1];
        p += nA * expf(S0 - acc[nt][0]) + nB * expf(S0 - acc[nt][1]);
        p += nA * expf(S1 - acc[nt][2]) + nB * expf(S1 - acc[nt][3]);
    }
    #pragma unroll
    for (int off = 16; off > 0; off >>= 1)
        p += __shfl_xor_sync(0xffffffffu, p, off);
    const double warp_neg = (double)p;

    double warp_sd = 0.0, warp_se = 0.0;
    if (warp == 0) {
        const float dv = g_d[row0 + lane];
        double sd = (double)dv;
        double se = (double)expf(dv);
        #pragma unroll
        for (int off = 16; off > 0; off >>= 1) {
            sd += __shfl_xor_sync(0xffffffffu, sd, off);
            se += __shfl_xor_sync(0xffffffffu, se, off);
        }
        warp_sd = sd; warp_se = se;
    }

    if (lane == 0) { bred[warp*3+0] = warp_neg; bred[warp*3+1] = warp_sd; bred[warp*3+2] = warp_se; }
    __syncthreads();

    if (tid == 0) {
        double bneg = 0.0;
        #pragma unroll
        for (int w = 0; w < 8; w++) bneg += bred[w*3+0];
        atomicAdd(&g_neg, bneg);
        atomicAdd(&g_sumd, bred[0*3+1]);
        atomicAdd(&g_sumexpd, bred[0*3+2]);
        __threadfence();
        unsigned t = atomicAdd(&g_fin, 1u);
        if (t == NBLK - 1) {
            // loss = N*log(neg) + sumexp/neg - sumd (validated across rounds)
            const double neg  = atomicAdd(&g_neg, 0.0);
            const double sd   = atomicAdd(&g_sumd, 0.0);
            const double sexp = atomicAdd(&g_sumexpd, 0.0);
            out[0] = (float)((double)N * log(neg) + sexp / neg - sd);
        }
    }

    // ---- self-cleaning tail (gated on EARLY event: all G/cnt reads done) ----
    // All 128 blocks are co-resident; every block signaled g_reads in its first
    // ~1us, so this spin is ~free by the time any block reaches it.
    if (tid == 0) {
        while (*(volatile unsigned int*)&g_reads < (unsigned)NBLK) __nanosleep(32);
    }
    __syncthreads();

    if (tid < 100) {   // block b zeroes its 100-float4 slice of G
        const float4 z4 = make_float4(0.f, 0.f, 0.f, 0.f);
        reinterpret_cast<float4*>(g_G)[blockIdx.x * 100 + tid] = z4;
    }
    if (blockIdx.x == 0 && tid < NCP) g_cnt[tid] = 0;
    __threadfence();
    __syncthreads();
    if (tid == 0) {
        unsigned c = atomicAdd(&g_cleanfin, 1u);
        if (c == NBLK - 1) {
            // 128th cleaner: loss already written (the loss-writer incremented
            // cleanfin only after writing out[0]) -> safe to reset scalars.
            g_neg = 0.0; g_sumd = 0.0; g_sumexpd = 0.0;
            g_fin = 0u; g_reads = 0u; g_cleanfin = 0u;
            __threadfence();
        }
    }
}

// ---------------------------------------------------------------------------
extern "C" void kernel_launch(void* const* d_in, const int* in_sizes, int n_in,
                              void* d_out, int out_size) {
    const float* img    = (const float*)d_in[0];
    const float* txt    = (const float*)d_in[1];
    const int*   labels = (const int*)d_in[2];
    float* out = (float*)d_out;

    cudaFuncSetAttribute(gemm_neg_kernel,
                         cudaFuncAttributeMaxDynamicSharedMemorySize, SMEM_BYTES);
    rownorm_kernel<<<N, 128>>>(img, txt, labels);
    gemm_neg_kernel<<<NBLK, 256, SMEM_BYTES>>>(out);
}

// round 13
// speedup vs baseline: 1.2742x; 1.2742x over previous
#include <cuda_runtime.h>
#include <cuda_bf16.h>

// Problem constants
#define N 4096
#define D 512
#define NC 100          // real classes
#define NCP 128         // padded classes
#define ROWS_B 32       // rows per GEMM block
#define KT 32           // k-tile
#define NBLK (N / ROWS_B)   // 128 gemm blocks

// Scratch (device globals; no allocation in kernel_launch)
__device__ float g_rscale[N];                     // per-row 1/||txt_i|| (overwritten every call)
__device__ float g_d[N];                          // per-row <img_n, txt_n>
__device__ __align__(16) float g_G[NC * D];       // class sums of img_n, [c][d]
__device__ int    g_cnt[NCP];                     // class counts
__device__ double g_neg;                          // neg accumulator
__device__ double g_sumd;                         // sum_i d_i
__device__ double g_sumexpd;                      // sum_i exp(d_i)
__device__ unsigned int g_fin;                    // epilogue ticket

__device__ __forceinline__ unsigned tf32(float x) {
    unsigned r;
    asm("cvt.rna.tf32.f32 %0, %1;" : "=r"(r) : "f"(x));
    return r;
}

// ---------------------------------------------------------------------------
// Kernel 0: zero scratch accumulators (runs every replay)
// ---------------------------------------------------------------------------
__global__ void zero_kernel() {
    const int idx = blockIdx.x * blockDim.x + threadIdx.x;
    const float4 z4 = make_float4(0.f, 0.f, 0.f, 0.f);
    if (idx < (NC * D) / 4) reinterpret_cast<float4*>(g_G)[idx] = z4;
    if (idx < NCP)          g_cnt[idx] = 0;
    if (idx == 0) { g_neg = 0.0; g_sumd = 0.0; g_sumexpd = 0.0; g_fin = 0u; }
}

// ---------------------------------------------------------------------------
// Kernel 1: normalize, store rscale + d_i, scatter img_n into G (v4 REDG).
// grid = N blocks, 128 threads (thread owns 4 consecutive dims, float4).
// Delta vs R10: NO 8MB txt_n store — only the 16KB rscale vector.
// ---------------------------------------------------------------------------
__global__ void __launch_bounds__(128) rownorm_kernel(
    const float* __restrict__ img,
    const float* __restrict__ txt,
    const int* __restrict__ labels)
{
    const int i    = blockIdx.x;
    const int tid  = threadIdx.x;
    const int lane = tid & 31;
    const int warp = tid >> 5;

    const float4 a = reinterpret_cast<const float4*>(img + (size_t)i * D)[tid];
    const float4 b = reinterpret_cast<const float4*>(txt + (size_t)i * D)[tid];

    float sii = a.x*a.x + a.y*a.y + a.z*a.z + a.w*a.w;
    float stt = b.x*b.x + b.y*b.y + b.z*b.z + b.w*b.w;
    float sit = a.x*b.x + a.y*b.y + a.z*b.z + a.w*b.w;

    #pragma unroll
    for (int off = 16; off > 0; off >>= 1) {
        sii += __shfl_xor_sync(0xffffffffu, sii, off);
        stt += __shfl_xor_sync(0xffffffffu, stt, off);
        sit += __shfl_xor_sync(0xffffffffu, sit, off);
    }
    __shared__ float red[3][4];
    if (lane == 0) { red[0][warp] = sii; red[1][warp] = stt; red[2][warp] = sit; }
    __syncthreads();
    sii = red[0][0] + red[0][1] + red[0][2] + red[0][3];
    stt = red[1][0] + red[1][1] + red[1][2] + red[1][3];
    sit = red[2][0] + red[2][1] + red[2][2] + red[2][3];

    const float rimg = rsqrtf(sii);
    const float rtxt = rsqrtf(stt);
    int c = labels[i];
    c = min(max(c, 0), NC - 1);

    // one vector reduction (16B-aligned) instead of 4 scalar REDs
    float* gc = g_G + (size_t)c * D + tid * 4;
    asm volatile("red.global.add.v4.f32 [%0], {%1, %2, %3, %4};"
                 :: "l"(gc), "f"(a.x * rimg), "f"(a.y * rimg),
                    "f"(a.z * rimg), "f"(a.w * rimg)
                 : "memory");

    if (tid == 0) {
        g_rscale[i] = rtxt;
        g_d[i] = sit * rimg * rtxt;
        atomicAdd(&g_cnt[c], 1);
    }
}

// ---------------------------------------------------------------------------
// Kernel 2 (R10-proven): tf32 mma GEMM + neg + folded finish.
// grid = 128 blocks, 256 threads (8 warps).
// Warp (m = w&1, nq = w>>1) owns rows 16m..16m+15 x classes 32nq..32nq+31.
// Delta vs R10: A loaded from RAW txt and scaled by rs[ar] at staging.
// ---------------------------------------------------------------------------
__global__ void __launch_bounds__(256) gemm_neg_kernel(
    const float* __restrict__ txt,
    float* __restrict__ out)
{
    __shared__ float As[ROWS_B][36];   // [row][k], tf32 bits, K-major
    __shared__ float Bs[NCP][36];      // [class][k], tf32 bits, K-major
    __shared__ float nsm[NCP];         // class counts as float
    __shared__ float rs[ROWS_B];       // per-row text scale
    __shared__ float Ssm[ROWS_B][4];   // per-row partial sums per class-quadrant
    __shared__ double bred[8][3];      // per-warp {neg, sumd, sumexp}

    const int tid  = threadIdx.x;
    const int lane = tid & 31;
    const int warp = tid >> 5;
    const int g    = lane >> 2;        // group id 0..7
    const int tig  = lane & 3;         // thread in group 0..3
    const int m    = warp & 1;         // row half
    const int nq   = warp >> 1;        // class quadrant 0..3
    const int row0 = blockIdx.x * ROWS_B;

    if (tid < NCP) nsm[tid] = (float)g_cnt[tid];
    if (tid < ROWS_B) rs[tid] = g_rscale[row0 + tid];

    float acc[4][4] = {};              // [n-tile][c0..c3]

    // staging addressing (constant per thread)
    const int ar  = tid >> 3;          // A row 0..31
    const int ak4 = (tid & 7) * 4;     // k offset 0..28
    const float4 zero4 = make_float4(0.f, 0.f, 0.f, 0.f);

    float4 aReg;
    float4 bReg[4];

    // prefetch tile 0 (raw txt)
    aReg = *reinterpret_cast<const float4*>(&txt[(size_t)(row0 + ar) * D + ak4]);
    #pragma unroll
    for (int e = 0; e < 4; e++) {
        int idx = tid + e * 256;
        int c = idx >> 3, k4 = (idx & 7) * 4;
        bReg[e] = (c < NC)
            ? *reinterpret_cast<const float4*>(&g_G[(size_t)c * D + k4])
            : zero4;
    }
    __syncthreads();   // rs / nsm visible
    const float ascale = rs[ar];

    for (int t = 0; t < D / KT; t++) {
        // commit prefetched tile to smem as tf32 bits (float4 STS.128)
        {
            float4 av;
            av.x = __uint_as_float(tf32(aReg.x * ascale));
            av.y = __uint_as_float(tf32(aReg.y * ascale));
            av.z = __uint_as_float(tf32(aReg.z * ascale));
            av.w = __uint_as_float(tf32(aReg.w * ascale));
            *reinterpret_cast<float4*>(&As[ar][ak4]) = av;
        }
        #pragma unroll
        for (int e = 0; e < 4; e++) {
            int idx = tid + e * 256;
            int c = idx >> 3, k4 = (idx & 7) * 4;
            float4 bv;
            bv.x = __uint_as_float(tf32(bReg[e].x));
            bv.y = __uint_as_float(tf32(bReg[e].y));
            bv.z = __uint_as_float(tf32(bReg[e].z));
            bv.w = __uint_as_float(tf32(bReg[e].w));
            *reinterpret_cast<float4*>(&Bs[c][k4]) = bv;
        }
        __syncthreads();

        // prefetch next tile (overlaps compute)
        if (t < D / KT - 1) {
            int k0 = (t + 1) * KT;
            aReg = *reinterpret_cast<const float4*>(&txt[(size_t)(row0 + ar) * D + k0 + ak4]);
            #pragma unroll
            for (int e = 0; e < 4; e++) {
                int idx = tid + e * 256;
                int c = idx >> 3, k4 = (idx & 7) * 4;
                bReg[e] = (c < NC)
                    ? *reinterpret_cast<const float4*>(&g_G[(size_t)c * D + k0 + k4])
                    : zero4;
            }
        }

        // compute: 4 k-subtiles of 8
        #pragma unroll
        for (int ks = 0; ks < 4; ks++) {
            const int kk0 = ks * 8;
            const unsigned a0 = __float_as_uint(As[16*m + g    ][kk0 + tig]);
            const unsigned a1 = __float_as_uint(As[16*m + g + 8][kk0 + tig]);
            const unsigned a2 = __float_as_uint(As[16*m + g    ][kk0 + tig + 4]);
            const unsigned a3 = __float_as_uint(As[16*m + g + 8][kk0 + tig + 4]);
            #pragma unroll
            for (int nt = 0; nt < 4; nt++) {
                const int cb = 32*nq + 8*nt + g;
                const unsigned b0 = __float_as_uint(Bs[cb][kk0 + tig]);
                const unsigned b1 = __float_as_uint(Bs[cb][kk0 + tig + 4]);
                asm volatile(
                    "mma.sync.aligned.m16n8k8.row.col.f32.tf32.tf32.f32 "
                    "{%0,%1,%2,%3}, {%4,%5,%6,%7}, {%8,%9}, {%0,%1,%2,%3};"
                    : "+f"(acc[nt][0]), "+f"(acc[nt][1]),
                      "+f"(acc[nt][2]), "+f"(acc[nt][3])
                    : "r"(a0), "r"(a1), "r"(a2), "r"(a3), "r"(b0), "r"(b1));
            }
        }
        __syncthreads();
    }

    // ---- Epilogue (R10-validated layout) ----
    // Thread holds C at rows r0=16m+g, r1=r0+8; cols 32nq+8nt+2tig(+1).
    float s0 = 0.f, s1 = 0.f;
    #pragma unroll
    for (int nt = 0; nt < 4; nt++) {
        s0 += acc[nt][0] + acc[nt][1];
        s1 += acc[nt][2] + acc[nt][3];
    }
    s0 += __shfl_xor_sync(0xffffffffu, s0, 1);
    s0 += __shfl_xor_sync(0xffffffffu, s0, 2);
    s1 += __shfl_xor_sync(0xffffffffu, s1, 1);
    s1 += __shfl_xor_sync(0xffffffffu, s1, 2);
    const int r0 = 16*m + g, r1 = r0 + 8;
    if (tig == 0) { Ssm[r0][nq] = s0; Ssm[r1][nq] = s1; }
    __syncthreads();

    const float S0 = Ssm[r0][0] + Ssm[r0][1] + Ssm[r0][2] + Ssm[r0][3];
    const float S1 = Ssm[r1][0] + Ssm[r1][1] + Ssm[r1][2] + Ssm[r1][3];
    float p = 0.f;
    #pragma unroll
    for (int nt = 0; nt < 4; nt++) {
        const int cA = 32*nq + 8*nt + 2*tig;
        const float nA = nsm[cA], nB = nsm[cA + 1];
        p += nA * expf(S0 - acc[nt][0]) + nB * expf(S0 - acc[nt][1]);
        p += nA * expf(S1 - acc[nt][2]) + nB * expf(S1 - acc[nt][3]);
    }
    #pragma unroll
    for (int off = 16; off > 0; off >>= 1)
        p += __shfl_xor_sync(0xffffffffu, p, off);
    const double warp_neg = (double)p;

    // warp 0: this block's sumd / sumexpd contribution
    double warp_sd = 0.0, warp_se = 0.0;
    if (warp == 0) {
        const float dv = g_d[row0 + lane];
        double sd = (double)dv;
        double se = (double)expf(dv);
        #pragma unroll
        for (int off = 16; off > 0; off >>= 1) {
            sd += __shfl_xor_sync(0xffffffffu, sd, off);
            se += __shfl_xor_sync(0xffffffffu, se, off);
        }
        warp_sd = sd; warp_se = se;
    }

    if (lane == 0) { bred[warp][0] = warp_neg; bred[warp][1] = warp_sd; bred[warp][2] = warp_se; }
    __syncthreads();

    if (tid == 0) {
        double bneg = 0.0;
        #pragma unroll
        for (int w = 0; w < 8; w++) bneg += bred[w][0];
        atomicAdd(&g_neg, bneg);
        atomicAdd(&g_sumd, bred[0][1]);
        atomicAdd(&g_sumexpd, bred[0][2]);
        __threadfence();
        unsigned t = atomicAdd(&g_fin, 1u);
        if (t == NBLK - 1) {
            // loss = N*log(neg) + sumexp/neg - sumd
            // (sum_i log1p(exp(d_i)/neg) == sumexp/neg to ~1e-10 abs since
            //  neg >= ~1e5 and exp(d_i) <= e; validated across rounds)
            const double neg  = atomicAdd(&g_neg, 0.0);
            const double sd   = atomicAdd(&g_sumd, 0.0);
            const double sexp = atomicAdd(&g_sumexpd, 0.0);
            out[0] = (float)((double)N * log(neg) + sexp / neg - sd);
        }
    }
}

// ---------------------------------------------------------------------------
extern "C" void kernel_launch(void* const* d_in, const int* in_sizes, int n_in,
                              void* d_out, int out_size) {
    const float* img    = (const float*)d_in[0];
    const float* txt    = (const float*)d_in[1];
    const int*   labels = (const int*)d_in[2];
    float* out = (float*)d_out;

    zero_kernel<<<((NC * D) / 4 + 255) / 256, 256>>>();
    rownorm_kernel<<<N, 128>>>(img, txt, labels);
    gemm_neg_kernel<<<NBLK, 256>>>(txt, out);
}

// round 14
// speedup vs baseline: 1.2759x; 1.0013x over previous
#include <cuda_runtime.h>
#include <cuda_bf16.h>

// Problem constants
#define N 4096
#define D 512
#define NC 100          // real classes
#define NCP 128         // padded classes
#define ROWS_B 32       // rows per GEMM block
#define KT 32           // k-tile
#define NBLK (N / ROWS_B)   // 128 gemm blocks

// Double-buffered scratch (device globals; load-time zeroed).
// Call with parity p: rownorm writes G[p]/cnt[p], gemm reads them and
// accumulates into scalars[p]; meanwhile every gemm block zeroes its slice of
// buffer q=1-p at entry (that buffer is idle this call -> no sync needed).
// Last gemm block flips parity after writing the result.
__device__ float g_rscale[N];                        // per-row 1/||txt_i||
__device__ float g_d[N];                             // per-row <img_n, txt_n>
__device__ __align__(16) float g_G[2][NC * D];       // class sums of img_n
__device__ int    g_cnt[2][NCP];                     // class counts
__device__ double g_neg[2];                          // neg accumulator
__device__ double g_sumd[2];                         // sum_i d_i
__device__ double g_sumexpd[2];                      // sum_i exp(d_i)
__device__ unsigned int g_fin[2];                    // epilogue ticket
__device__ unsigned int g_parity;                    // current buffer index

__device__ __forceinline__ unsigned tf32(float x) {
    unsigned r;
    asm("cvt.rna.tf32.f32 %0, %1;" : "=r"(r) : "f"(x));
    return r;
}

// ---------------------------------------------------------------------------
// Kernel 1: normalize, store rscale + d_i, scatter img_n into G[p] (v4 REDG).
// grid = N blocks, 128 threads (thread owns 4 consecutive dims, float4).
// ---------------------------------------------------------------------------
__global__ void __launch_bounds__(128) rownorm_kernel(
    const float* __restrict__ img,
    const float* __restrict__ txt,
    const int* __restrict__ labels)
{
    const int i    = blockIdx.x;
    const int tid  = threadIdx.x;
    const int lane = tid & 31;
    const int warp = tid >> 5;
    const unsigned p = g_parity;   // stable during this kernel

    const float4 a = reinterpret_cast<const float4*>(img + (size_t)i * D)[tid];
    const float4 b = reinterpret_cast<const float4*>(txt + (size_t)i * D)[tid];

    float sii = a.x*a.x + a.y*a.y + a.z*a.z + a.w*a.w;
    float stt = b.x*b.x + b.y*b.y + b.z*b.z + b.w*b.w;
    float sit = a.x*b.x + a.y*b.y + a.z*b.z + a.w*b.w;

    #pragma unroll
    for (int off = 16; off > 0; off >>= 1) {
        sii += __shfl_xor_sync(0xffffffffu, sii, off);
        stt += __shfl_xor_sync(0xffffffffu, stt, off);
        sit += __shfl_xor_sync(0xffffffffu, sit, off);
    }
    __shared__ float red[3][4];
    if (lane == 0) { red[0][warp] = sii; red[1][warp] = stt; red[2][warp] = sit; }
    __syncthreads();
    sii = red[0][0] + red[0][1] + red[0][2] + red[0][3];
    stt = red[1][0] + red[1][1] + red[1][2] + red[1][3];
    sit = red[2][0] + red[2][1] + red[2][2] + red[2][3];

    const float rimg = rsqrtf(sii);
    const float rtxt = rsqrtf(stt);
    int c = labels[i];
    c = min(max(c, 0), NC - 1);

    // one vector reduction (16B-aligned) instead of 4 scalar REDs
    float* gc = g_G[p] + (size_t)c * D + tid * 4;
    asm volatile("red.global.add.v4.f32 [%0], {%1, %2, %3, %4};"
                 :: "l"(gc), "f"(a.x * rimg), "f"(a.y * rimg),
                    "f"(a.z * rimg), "f"(a.w * rimg)
                 : "memory");

    if (tid == 0) {
        g_rscale[i] = rtxt;
        g_d[i] = sit * rimg * rtxt;
        atomicAdd(&g_cnt[p][c], 1);
    }
}

// ---------------------------------------------------------------------------
// Kernel 2 (R10-proven core): tf32 mma GEMM + neg + folded finish
//                             + zero-wait cleaning of the idle buffer.
// grid = 128 blocks, 256 threads (8 warps).
// Warp (m = w&1, nq = w>>1) owns rows 16m..16m+15 x classes 32nq..32nq+31.
// ---------------------------------------------------------------------------
__global__ void __launch_bounds__(256) gemm_neg_kernel(
    const float* __restrict__ txt,
    float* __restrict__ out)
{
    __shared__ float As[ROWS_B][36];   // [row][k], tf32 bits, K-major
    __shared__ float Bs[NCP][36];      // [class][k], tf32 bits, K-major
    __shared__ float nsm[NCP];         // class counts as float
    __shared__ float rs[ROWS_B];       // per-row text scale
    __shared__ float Ssm[ROWS_B][4];   // per-row partial sums per class-quadrant
    __shared__ double bred[8][3];      // per-warp {neg, sumd, sumexp}

    const int tid  = threadIdx.x;
    const int lane = tid & 31;
    const int warp = tid >> 5;
    const int g    = lane >> 2;        // group id 0..7
    const int tig  = lane & 3;         // thread in group 0..3
    const int m    = warp & 1;         // row half
    const int nq   = warp >> 1;        // class quadrant 0..3
    const int row0 = blockIdx.x * ROWS_B;
    const unsigned p = g_parity;       // stable during this kernel
    const unsigned q = 1u - p;

    // ---- zero-wait cleaning of the IDLE buffer q (untouched this call) ----
    if (tid < 100) {
        const float4 z4 = make_float4(0.f, 0.f, 0.f, 0.f);
        reinterpret_cast<float4*>(g_G[q])[blockIdx.x * 100 + tid] = z4;
    }
    if (blockIdx.x == 0) {
        if (tid < NCP) g_cnt[q][tid] = 0;
        if (tid == 0) { g_neg[q] = 0.0; g_sumd[q] = 0.0; g_sumexpd[q] = 0.0; g_fin[q] = 0u; }
    }

    if (tid < NCP) nsm[tid] = (float)g_cnt[p][tid];
    if (tid < ROWS_B) rs[tid] = g_rscale[row0 + tid];

    float acc[4][4] = {};              // [n-tile][c0..c3]

    // staging addressing (constant per thread)
    const int ar  = tid >> 3;          // A row 0..31
    const int ak4 = (tid & 7) * 4;     // k offset 0..28
    const float4 zero4 = make_float4(0.f, 0.f, 0.f, 0.f);

    float4 aReg;
    float4 bReg[4];

    // prefetch tile 0 (raw txt)
    aReg = *reinterpret_cast<const float4*>(&txt[(size_t)(row0 + ar) * D + ak4]);
    #pragma unroll
    for (int e = 0; e < 4; e++) {
        int idx = tid + e * 256;
        int c = idx >> 3, k4 = (idx & 7) * 4;
        bReg[e] = (c < NC)
            ? *reinterpret_cast<const float4*>(&g_G[p][(size_t)c * D + k4])
            : zero4;
    }
    __syncthreads();   // rs / nsm visible
    const float ascale = rs[ar];

    for (int t = 0; t < D / KT; t++) {
        // commit prefetched tile to smem as tf32 bits (float4 STS.128)
        {
            float4 av;
            av.x = __uint_as_float(tf32(aReg.x * ascale));
            av.y = __uint_as_float(tf32(aReg.y * ascale));
            av.z = __uint_as_float(tf32(aReg.z * ascale));
            av.w = __uint_as_float(tf32(aReg.w * ascale));
            *reinterpret_cast<float4*>(&As[ar][ak4]) = av;
        }
        #pragma unroll
        for (int e = 0; e < 4; e++) {
            int idx = tid + e * 256;
            int c = idx >> 3, k4 = (idx & 7) * 4;
            float4 bv;
            bv.x = __uint_as_float(tf32(bReg[e].x));
            bv.y = __uint_as_float(tf32(bReg[e].y));
            bv.z = __uint_as_float(tf32(bReg[e].z));
            bv.w = __uint_as_float(tf32(bReg[e].w));
            *reinterpret_cast<float4*>(&Bs[c][k4]) = bv;
        }
        __syncthreads();

        // prefetch next tile (overlaps compute)
        if (t < D / KT - 1) {
            int k0 = (t + 1) * KT;
            aReg = *reinterpret_cast<const float4*>(&txt[(size_t)(row0 + ar) * D + k0 + ak4]);
            #pragma unroll
            for (int e = 0; e < 4; e++) {
                int idx = tid + e * 256;
                int c = idx >> 3, k4 = (idx & 7) * 4;
                bReg[e] = (c < NC)
                    ? *reinterpret_cast<const float4*>(&g_G[p][(size_t)c * D + k0 + k4])
                    : zero4;
            }
        }

        // compute: 4 k-subtiles of 8
        #pragma unroll
        for (int ks = 0; ks < 4; ks++) {
            const int kk0 = ks * 8;
            const unsigned a0 = __float_as_uint(As[16*m + g    ][kk0 + tig]);
            const unsigned a1 = __float_as_uint(As[16*m + g + 8][kk0 + tig]);
            const unsigned a2 = __float_as_uint(As[16*m + g    ][kk0 + tig + 4]);
            const unsigned a3 = __float_as_uint(As[16*m + g + 8][kk0 + tig + 4]);
            #pragma unroll
            for (int nt = 0; nt < 4; nt++) {
                const int cb = 32*nq + 8*nt + g;
                const unsigned b0 = __float_as_uint(Bs[cb][kk0 + tig]);
                const unsigned b1 = __float_as_uint(Bs[cb][kk0 + tig + 4]);
                asm volatile(
                    "mma.sync.aligned.m16n8k8.row.col.f32.tf32.tf32.f32 "
                    "{%0,%1,%2,%3}, {%4,%5,%6,%7}, {%8,%9}, {%0,%1,%2,%3};"
                    : "+f"(acc[nt][0]), "+f"(acc[nt][1]),
                      "+f"(acc[nt][2]), "+f"(acc[nt][3])
                    : "r"(a0), "r"(a1), "r"(a2), "r"(a3), "r"(b0), "r"(b1));
            }
        }
        __syncthreads();
    }

    // ---- Epilogue (R10-validated layout) ----
    // Thread holds C at rows r0=16m+g, r1=r0+8; cols 32nq+8nt+2tig(+1).
    float s0 = 0.f, s1 = 0.f;
    #pragma unroll
    for (int nt = 0; nt < 4; nt++) {
        s0 += acc[nt][0] + acc[nt][1];
        s1 += acc[nt][2] + acc[nt][3];
    }
    s0 += __shfl_xor_sync(0xffffffffu, s0, 1);
    s0 += __shfl_xor_sync(0xffffffffu, s0, 2);
    s1 += __shfl_xor_sync(0xffffffffu, s1, 1);
    s1 += __shfl_xor_sync(0xffffffffu, s1, 2);
    const int r0 = 16*m + g, r1 = r0 + 8;
    if (tig == 0) { Ssm[r0][nq] = s0; Ssm[r1][nq] = s1; }
    __syncthreads();

    const float S0 = Ssm[r0][0] + Ssm[r0][1] + Ssm[r0][2] + Ssm[r0][3];
    const float S1 = Ssm[r1][0] + Ssm[r1][1] + Ssm[r1][2] + Ssm[r1][3];
    float pn = 0.f;
    #pragma unroll
    for (int nt = 0; nt < 4; nt++) {
        const int cA = 32*nq + 8*nt + 2*tig;
        const float nA = nsm[cA], nB = nsm[cA + 1];
        pn += nA * expf(S0 - acc[nt][0]) + nB * expf(S0 - acc[nt][1]);
        pn += nA * expf(S1 - acc[nt][2]) + nB * expf(S1 - acc[nt][3]);
    }
    #pragma unroll
    for (int off = 16; off > 0; off >>= 1)
        pn += __shfl_xor_sync(0xffffffffu, pn, off);
    const double warp_neg = (double)pn;

    // warp 0: this block's sumd / sumexpd contribution
    double warp_sd = 0.0, warp_se = 0.0;
    if (warp == 0) {
        const float dv = g_d[row0 + lane];
        double sd = (double)dv;
        double se = (double)expf(dv);
        #pragma unroll
        for (int off = 16; off > 0; off >>= 1) {
            sd += __shfl_xor_sync(0xffffffffu, sd, off);
            se += __shfl_xor_sync(0xffffffffu, se, off);
        }
        warp_sd = sd; warp_se = se;
    }

    if (lane == 0) { bred[warp][0] = warp_neg; bred[warp][1] = warp_sd; bred[warp][2] = warp_se; }
    __syncthreads();

    if (tid == 0) {
        double bneg = 0.0;
        #pragma unroll
        for (int w = 0; w < 8; w++) bneg += bred[w][0];
        atomicAdd(&g_neg[p], bneg);
        atomicAdd(&g_sumd[p], bred[0][1]);
        atomicAdd(&g_sumexpd[p], bred[0][2]);
        // fence orders BOTH the scalar adds above AND this block's cleaning
        // stores (buffer q) before the ticket increment.
        __threadfence();
        unsigned t = atomicAdd(&g_fin[p], 1u);
        if (t == NBLK - 1) {
            // loss = N*log(neg) + sumexp/neg - sumd (validated across rounds)
            const double neg  = atomicAdd(&g_neg[p], 0.0);
            const double sd   = atomicAdd(&g_sumd[p], 0.0);
            const double sexp = atomicAdd(&g_sumexpd[p], 0.0);
            out[0] = (float)((double)N * log(neg) + sexp / neg - sd);
            // all 128 tickets in => all blocks' cleaning of buffer q is
            // fenced-visible => safe to hand buffer q to the next call.
            __threadfence();
            g_parity = q;
        }
    }
}

// ---------------------------------------------------------------------------
extern "C" void kernel_launch(void* const* d_in, const int* in_sizes, int n_in,
                              void* d_out, int out_size) {
    const float* img    = (const float*)d_in[0];
    const float* txt    = (const float*)d_in[1];
    const int*   labels = (const int*)d_in[2];
    float* out = (float*)d_out;

    rownorm_kernel<<<N, 128>>>(img, txt, labels);
    gemm_neg_kernel<<<NBLK, 256>>>(txt, out);
}